// round 9
// baseline (speedup 1.0000x reference)
#include <cuda_runtime.h>
#include <cuda_fp16.h>
#include <cstdint>

#define T_STEPS 365
#define NCELL   65536
#define BD      224      // 7 warps * 32
#define CPB     112      // cells per block (7 warps * 16)
#define GRID    586      // ceil(65536/112)
#define KSTR    72       // padded k stride (fp16 elems) for conflict-free ldmatrix

#define OFF_W   0
#define OFF_PK  (192*KSTR*2)           // 27648
#define SMEM_BYTES (OFF_PK + 32*6*16)  // 30720

// ---------- helpers ----------
__device__ __forceinline__ uint32_t smem_u32(const void* p) {
    uint32_t r;
    asm("{ .reg .u64 t; cvta.to.shared.u64 t, %1; cvt.u32.u64 %0, t; }" : "=r"(r) : "l"(p));
    return r;
}
__device__ __forceinline__ uint32_t h2u(__half2 h) { return *(uint32_t*)&h; }

__device__ __forceinline__ void mma16816(float* c, const uint32_t* a, const uint32_t* b) {
    asm volatile(
        "mma.sync.aligned.m16n8k16.row.col.f32.f16.f16.f32 "
        "{%0,%1,%2,%3}, {%4,%5,%6,%7}, {%8,%9}, {%0,%1,%2,%3};"
        : "+f"(c[0]), "+f"(c[1]), "+f"(c[2]), "+f"(c[3])
        : "r"(a[0]), "r"(a[1]), "r"(a[2]), "r"(a[3]), "r"(b[0]), "r"(b[1]));
}
__device__ __forceinline__ void ldsm4(uint32_t* r, uint32_t addr) {
    asm volatile("ldmatrix.sync.aligned.m8n8.x4.shared.b16 {%0,%1,%2,%3}, [%4];"
                 : "=r"(r[0]), "=r"(r[1]), "=r"(r[2]), "=r"(r[3]) : "r"(addr));
}
// reset gate only: sigmoid via tanh.approx (1 MUFU, error heavily damped downstream)
__device__ __forceinline__ float sigt(float x) {
    float r;
    asm("tanh.approx.f32 %0, %1;" : "=f"(r) : "f"(0.5f * x));
    return fmaf(0.5f, r, 0.5f);
}
// accurate sigmoid: 1/(1+2^(-x*log2e))  (2 MUFU, err ~1e-6)
__device__ __forceinline__ float siga(float x) {
    float e, r;
    asm("ex2.approx.f32 %0, %1;" : "=f"(e) : "f"(-1.4426950408889634f * x));
    asm("rcp.approx.f32 %0, %1;" : "=f"(r) : "f"(e + 1.0f));
    return r;
}
// accurate tanh: 1 - 2/(e^{2x}+1)  (2 MUFU, err ~1e-6)
__device__ __forceinline__ float tanha(float x) {
    float e, r;
    asm("ex2.approx.f32 %0, %1;" : "=f"(e) : "f"(2.8853900817779268f * x));
    asm("rcp.approx.f32 %0, %1;" : "=f"(r) : "f"(e + 1.0f));
    return fmaf(-2.0f, r, 1.0f);
}

extern __shared__ char smc[];

__global__ __launch_bounds__(BD, 2)
void gru_mma_kernel(const float* __restrict__ pr, const float* __restrict__ te,
                    const float* __restrict__ wih, const float* __restrict__ whh,
                    const float* __restrict__ bias, const float* __restrict__ bias_n,
                    const float* __restrict__ outw, const float* __restrict__ outb,
                    const float* __restrict__ init_h, float* __restrict__ out) {
    const int tid = threadIdx.x;

    // ---- W_hh fp16 tile in smem: [n=192][k padded to KSTR] ----
    for (int p = tid; p < 192 * 32; p += BD) {
        int n = p >> 5, kp = p & 31;
        __half2 w = __floats2half2_rn(whh[n * 64 + 2 * kp], whh[n * 64 + 2 * kp + 1]);
        *(uint32_t*)(smc + OFF_W + (uint32_t)(n * KSTR + 2 * kp) * 2) = h2u(w);
    }
    // ---- packed scalar params per unit-pair p: units {2p, 2p+1} ----
    if (tid < 32) {
        int p = tid, a = 2 * p, b = a + 1;
        float4* pk = (float4*)(smc + OFF_PK) + p * 6;
        pk[0] = make_float4(wih[2*a], wih[2*a+1], bias[a], wih[2*b]);
        pk[1] = make_float4(wih[2*b+1], bias[b], wih[2*(64+a)], wih[2*(64+a)+1]);
        pk[2] = make_float4(bias[64+a], wih[2*(64+b)], wih[2*(64+b)+1], bias[64+b]);
        pk[3] = make_float4(wih[2*(128+a)], wih[2*(128+a)+1], bias[128+a], wih[2*(128+b)]);
        pk[4] = make_float4(wih[2*(128+b)+1], bias[128+b], bias_n[a], bias_n[b]);
        pk[5] = make_float4(outw[a], outw[b], 0.0f, 0.0f);
    }
    __syncthreads();

    const int warp = tid >> 5, lane = tid & 31;
    const int gid = lane >> 2, q = lane & 3;
    const int cellbase = blockIdx.x * CPB + warp * 16;
    const int c0 = cellbase + gid, c8 = c0 + 8;
    const int c0c = min(c0, NCELL - 1), c8c = min(c8, NCELL - 1);
    const bool v0 = c0 < NCELL, v8 = c8 < NCELL;

    const uint32_t sb = smem_u32(smc) + OFF_W;
    const uint32_t lmoff = (uint32_t)((lane & 7) * KSTR + (lane >> 3) * 8) * 2;
    const float4* pkbase = (const float4*)(smc + OFF_PK);

    // ---- fp32 hidden state: hs0/hs8[2j+{0,1}] = h[row gid / gid+8][unit 8j+2q+{0,1}]
    float hs0[16], hs8[16];
    #pragma unroll
    for (int j = 0; j < 8; j++) {
        const int u = 8 * j + 2 * q;
        hs0[2*j] = init_h[u]; hs0[2*j+1] = init_h[u + 1];
        hs8[2*j] = init_h[u]; hs8[2*j+1] = init_h[u + 1];
    }
    const float ob = outb[0];

    for (int t = 0; t < T_STEPS; t++) {
        const size_t base = (size_t)t * NCELL;
        const float xp0 = pr[base + c0c], xp8 = pr[base + c8c];
        const float xt0 = te[base + c0c], xt8 = te[base + c8c];

        // ---- pack frozen fp16 hi/lo A fragments from fp32 state ----
        // reg order per kt: 0 = row g / k-lo, 1 = row g+8 / k-lo, 2 = row g / k-hi, 3 = row g+8 / k-hi
        uint32_t AH[4][4], AL[4][4];
        #pragma unroll
        for (int kt = 0; kt < 4; kt++) {
            #pragma unroll
            for (int hh = 0; hh < 2; hh++) {
                const int j = 2 * kt + hh;
                __half2 p0 = __floats2half2_rn(hs0[2*j], hs0[2*j+1]);
                float2 f0 = __half22float2(p0);
                AH[kt][2*hh] = h2u(p0);
                AL[kt][2*hh] = h2u(__floats2half2_rn(hs0[2*j] - f0.x, hs0[2*j+1] - f0.y));
                __half2 p8 = __floats2half2_rn(hs8[2*j], hs8[2*j+1]);
                float2 f8 = __half22float2(p8);
                AH[kt][2*hh+1] = h2u(p8);
                AL[kt][2*hh+1] = h2u(__floats2half2_rn(hs8[2*j] - f8.x, hs8[2*j+1] - f8.y));
            }
        }

        float y0 = 0.0f, y8 = 0.0f;

        #pragma unroll
        for (int j = 0; j < 8; j++) {
            // r and z gates: hi-pass only (fp16-h residual damped by sigmoid + small gains)
            float cr[4], cz[4], cnA[4], cnB[4];
            uint32_t bfr[8], bfz[8], bfn[8];
            const uint32_t wof0 = (uint32_t)(8 * j) * (KSTR * 2);
            const uint32_t wof1 = (uint32_t)(64 + 8 * j) * (KSTR * 2);
            const uint32_t wof2 = (uint32_t)(128 + 8 * j) * (KSTR * 2);
            ldsm4(bfr,     sb + wof0 + lmoff);
            ldsm4(bfr + 4, sb + wof0 + lmoff + 64);
            ldsm4(bfz,     sb + wof1 + lmoff);
            ldsm4(bfz + 4, sb + wof1 + lmoff + 64);
            ldsm4(bfn,     sb + wof2 + lmoff);
            ldsm4(bfn + 4, sb + wof2 + lmoff + 64);
            cr[0]=cr[1]=cr[2]=cr[3]=0.0f;
            cz[0]=cz[1]=cz[2]=cz[3]=0.0f;
            cnA[0]=cnA[1]=cnA[2]=cnA[3]=0.0f;
            cnB[0]=cnB[1]=cnB[2]=cnB[3]=0.0f;
            #pragma unroll
            for (int k2 = 0; k2 < 4; k2++) {
                mma16816(cr,  AH[k2], bfr + 2 * k2);
                mma16816(cz,  AH[k2], bfz + 2 * k2);
                mma16816(cnA, AH[k2], bfn + 2 * k2);   // hi chain
                mma16816(cnB, AL[k2], bfn + 2 * k2);   // lo chain (independent)
            }
            const float cn0 = cnA[0] + cnB[0];
            const float cn1 = cnA[1] + cnB[1];
            const float cn2 = cnA[2] + cnB[2];
            const float cn3 = cnA[3] + cnB[3];

            // ---- epilogue: units a=8j+2q, b=a+1, rows gid and gid+8 ----
            const float4* pp = pkbase + (4 * j + q) * 6;
            const float4 k0 = pp[0], k1 = pp[1], k2 = pp[2], k3 = pp[3], k4 = pp[4], k5 = pp[5];

            const float ra0 = sigt(fmaf(xp0, k0.x, fmaf(xt0, k0.y, k0.z)) + cr[0]);
            const float rb0 = sigt(fmaf(xp0, k0.w, fmaf(xt0, k1.x, k1.y)) + cr[1]);
            const float ra8 = sigt(fmaf(xp8, k0.x, fmaf(xt8, k0.y, k0.z)) + cr[2]);
            const float rb8 = sigt(fmaf(xp8, k0.w, fmaf(xt8, k1.x, k1.y)) + cr[3]);

            const float za0 = siga(fmaf(xp0, k1.z, fmaf(xt0, k1.w, k2.x)) + cz[0]);
            const float zb0 = siga(fmaf(xp0, k2.y, fmaf(xt0, k2.z, k2.w)) + cz[1]);
            const float za8 = siga(fmaf(xp8, k1.z, fmaf(xt8, k1.w, k2.x)) + cz[2]);
            const float zb8 = siga(fmaf(xp8, k2.y, fmaf(xt8, k2.z, k2.w)) + cz[3]);

            const float nva0 = tanha(fmaf(ra0, cn0 + k4.z, fmaf(xp0, k3.x, fmaf(xt0, k3.y, k3.z))));
            const float nvb0 = tanha(fmaf(rb0, cn1 + k4.w, fmaf(xp0, k3.w, fmaf(xt0, k4.x, k4.y))));
            const float nva8 = tanha(fmaf(ra8, cn2 + k4.z, fmaf(xp8, k3.x, fmaf(xt8, k3.y, k3.z))));
            const float nvb8 = tanha(fmaf(rb8, cn3 + k4.w, fmaf(xp8, k3.w, fmaf(xt8, k4.x, k4.y))));

            const float nha0 = fmaf(za0, hs0[2*j]   - nva0, nva0);
            const float nhb0 = fmaf(zb0, hs0[2*j+1] - nvb0, nvb0);
            const float nha8 = fmaf(za8, hs8[2*j]   - nva8, nva8);
            const float nhb8 = fmaf(zb8, hs8[2*j+1] - nvb8, nvb8);

            hs0[2*j] = nha0; hs0[2*j+1] = nhb0;
            hs8[2*j] = nha8; hs8[2*j+1] = nhb8;

            y0 = fmaf(k5.x, nha0, fmaf(k5.y, nhb0, y0));
            y8 = fmaf(k5.x, nha8, fmaf(k5.y, nhb8, y8));
        }

        // quad reduce y (lanes within a quad differ only in q)
        y0 += __shfl_xor_sync(0xffffffff, y0, 1);
        y0 += __shfl_xor_sync(0xffffffff, y0, 2);
        y8 += __shfl_xor_sync(0xffffffff, y8, 1);
        y8 += __shfl_xor_sync(0xffffffff, y8, 2);
        if (q == 0) {
            if (v0) out[base + c0] = y0 + ob;
            if (v8) out[base + c8] = y8 + ob;
        }
    }

    // ---- final hidden state (N, 64), fp32 state written directly ----
    float* fo = out + (size_t)T_STEPS * NCELL;
    #pragma unroll
    for (int j = 0; j < 8; j++) {
        const int u = 8 * j + 2 * q;
        if (v0) *(float2*)(fo + (size_t)c0 * 64 + u) = make_float2(hs0[2*j], hs0[2*j+1]);
        if (v8) *(float2*)(fo + (size_t)c8 * 64 + u) = make_float2(hs8[2*j], hs8[2*j+1]);
    }
}

extern "C" void kernel_launch(void* const* d_in, const int* in_sizes, int n_in,
                              void* d_out, int out_size) {
    const float* pr     = (const float*)d_in[0];
    const float* te     = (const float*)d_in[1];
    const float* wih    = (const float*)d_in[2];
    const float* whh    = (const float*)d_in[3];
    const float* bias   = (const float*)d_in[4];
    const float* bias_n = (const float*)d_in[5];
    const float* outw   = (const float*)d_in[6];
    const float* outb   = (const float*)d_in[7];
    const float* init_h = (const float*)d_in[8];
    float* out = (float*)d_out;

    cudaFuncSetAttribute(gru_mma_kernel,
                         cudaFuncAttributeMaxDynamicSharedMemorySize, SMEM_BYTES);

    gru_mma_kernel<<<GRID, BD, SMEM_BYTES>>>(pr, te, wih, whh, bias, bias_n,
                                             outw, outb, init_h, out);
}

// round 11
// speedup vs baseline: 1.5168x; 1.5168x over previous
#include <cuda_runtime.h>
#include <cuda_fp16.h>
#include <cstdint>

#define T_STEPS 365
#define NCELL   65536
#define BD      224      // 7 warps * 32
#define CPB     112      // cells per block (7 warps * 16)
#define GRID    586      // ceil(65536/112)
#define KSTR    72       // padded k stride (fp16 elems) for conflict-free ldmatrix

#define OFF_W   0
#define OFF_PK  (192*KSTR*2)           // 27648
#define SMEM_BYTES (OFF_PK + 32*6*16)  // 30720

// ---------- helpers ----------
__device__ __forceinline__ uint32_t smem_u32(const void* p) {
    uint32_t r;
    asm("{ .reg .u64 t; cvta.to.shared.u64 t, %1; cvt.u32.u64 %0, t; }" : "=r"(r) : "l"(p));
    return r;
}
__device__ __forceinline__ uint32_t h2u(__half2 h) { return *(uint32_t*)&h; }

__device__ __forceinline__ void mma16816(float* c, const uint32_t* a, const uint32_t* b) {
    asm volatile(
        "mma.sync.aligned.m16n8k16.row.col.f32.f16.f16.f32 "
        "{%0,%1,%2,%3}, {%4,%5,%6,%7}, {%8,%9}, {%0,%1,%2,%3};"
        : "+f"(c[0]), "+f"(c[1]), "+f"(c[2]), "+f"(c[3])
        : "r"(a[0]), "r"(a[1]), "r"(a[2]), "r"(a[3]), "r"(b[0]), "r"(b[1]));
}
__device__ __forceinline__ void ldsm4(uint32_t* r, uint32_t addr) {
    asm volatile("ldmatrix.sync.aligned.m8n8.x4.shared.b16 {%0,%1,%2,%3}, [%4];"
                 : "=r"(r[0]), "=r"(r[1]), "=r"(r[2]), "=r"(r[3]) : "r"(addr));
}
// reset gate only: sigmoid via tanh.approx (1 MUFU, error heavily damped downstream)
__device__ __forceinline__ float sigt(float x) {
    float r;
    asm("tanh.approx.f32 %0, %1;" : "=f"(r) : "f"(0.5f * x));
    return fmaf(0.5f, r, 0.5f);
}
// accurate sigmoid: 1/(1+2^(-x*log2e))  (2 MUFU, err ~1e-6)
__device__ __forceinline__ float siga(float x) {
    float e, r;
    asm("ex2.approx.f32 %0, %1;" : "=f"(e) : "f"(-1.4426950408889634f * x));
    asm("rcp.approx.f32 %0, %1;" : "=f"(r) : "f"(e + 1.0f));
    return r;
}
// accurate tanh: 1 - 2/(e^{2x}+1)  (2 MUFU, err ~1e-6)
__device__ __forceinline__ float tanha(float x) {
    float e, r;
    asm("ex2.approx.f32 %0, %1;" : "=f"(e) : "f"(2.8853900817779268f * x));
    asm("rcp.approx.f32 %0, %1;" : "=f"(r) : "f"(e + 1.0f));
    return fmaf(-2.0f, r, 1.0f);
}

extern __shared__ char smc[];

__global__ __launch_bounds__(BD, 2)
void gru_mma_kernel(const float* __restrict__ pr, const float* __restrict__ te,
                    const float* __restrict__ wih, const float* __restrict__ whh,
                    const float* __restrict__ bias, const float* __restrict__ bias_n,
                    const float* __restrict__ outw, const float* __restrict__ outb,
                    const float* __restrict__ init_h, float* __restrict__ out) {
    const int tid = threadIdx.x;

    // ---- W_hh fp16 tile in smem: [n=192][k padded to KSTR] ----
    for (int p = tid; p < 192 * 32; p += BD) {
        int n = p >> 5, kp = p & 31;
        __half2 w = __floats2half2_rn(whh[n * 64 + 2 * kp], whh[n * 64 + 2 * kp + 1]);
        *(uint32_t*)(smc + OFF_W + (uint32_t)(n * KSTR + 2 * kp) * 2) = h2u(w);
    }
    // ---- packed scalar params per unit-pair p: units {2p, 2p+1} ----
    if (tid < 32) {
        int p = tid, a = 2 * p, b = a + 1;
        float4* pk = (float4*)(smc + OFF_PK) + p * 6;
        pk[0] = make_float4(wih[2*a], wih[2*a+1], bias[a], wih[2*b]);
        pk[1] = make_float4(wih[2*b+1], bias[b], wih[2*(64+a)], wih[2*(64+a)+1]);
        pk[2] = make_float4(bias[64+a], wih[2*(64+b)], wih[2*(64+b)+1], bias[64+b]);
        pk[3] = make_float4(wih[2*(128+a)], wih[2*(128+a)+1], bias[128+a], wih[2*(128+b)]);
        pk[4] = make_float4(wih[2*(128+b)+1], bias[128+b], bias_n[a], bias_n[b]);
        pk[5] = make_float4(outw[a], outw[b], 0.0f, 0.0f);
    }
    __syncthreads();

    const int warp = tid >> 5, lane = tid & 31;
    const int gid = lane >> 2, q = lane & 3;
    const int cellbase = blockIdx.x * CPB + warp * 16;
    const int c0 = cellbase + gid, c8 = c0 + 8;
    const int c0c = min(c0, NCELL - 1), c8c = min(c8, NCELL - 1);
    const bool v0 = c0 < NCELL, v8 = c8 < NCELL;

    const uint32_t sb = smem_u32(smc) + OFF_W;
    const uint32_t lmoff = (uint32_t)((lane & 7) * KSTR + (lane >> 3) * 8) * 2;
    const float4* pkbase = (const float4*)(smc + OFF_PK);

    // ---- fp32 hidden state: hs0/hs8[2j+{0,1}] = h[row gid / gid+8][unit 8j+2q+{0,1}]
    float hs0[16], hs8[16];
    #pragma unroll
    for (int j = 0; j < 8; j++) {
        const int u = 8 * j + 2 * q;
        hs0[2*j] = init_h[u]; hs0[2*j+1] = init_h[u + 1];
        hs8[2*j] = init_h[u]; hs8[2*j+1] = init_h[u + 1];
    }
    const float ob = outb[0];

    for (int t = 0; t < T_STEPS; t++) {
        const size_t base = (size_t)t * NCELL;
        const float xp0 = pr[base + c0c], xp8 = pr[base + c8c];
        const float xt0 = te[base + c0c], xt8 = te[base + c8c];

        // ---- pack frozen fp16 hi/lo A fragments from fp32 state ----
        // reg order per kt: 0 = row g / k-lo, 1 = row g+8 / k-lo, 2 = row g / k-hi, 3 = row g+8 / k-hi
        uint32_t AH[4][4], AL[4][4];
        #pragma unroll
        for (int kt = 0; kt < 4; kt++) {
            #pragma unroll
            for (int hh = 0; hh < 2; hh++) {
                const int j = 2 * kt + hh;
                __half2 p0 = __floats2half2_rn(hs0[2*j], hs0[2*j+1]);
                float2 f0 = __half22float2(p0);
                AH[kt][2*hh] = h2u(p0);
                AL[kt][2*hh] = h2u(__floats2half2_rn(hs0[2*j] - f0.x, hs0[2*j+1] - f0.y));
                __half2 p8 = __floats2half2_rn(hs8[2*j], hs8[2*j+1]);
                float2 f8 = __half22float2(p8);
                AH[kt][2*hh+1] = h2u(p8);
                AL[kt][2*hh+1] = h2u(__floats2half2_rn(hs8[2*j] - f8.x, hs8[2*j+1] - f8.y));
            }
        }

        float y0 = 0.0f, y8 = 0.0f;

        #pragma unroll
        for (int j = 0; j < 8; j++) {
            float c[3][4];
            #pragma unroll
            for (int g = 0; g < 3; g++) {
                uint32_t bf[8];
                const uint32_t nb = (uint32_t)(g * 64 + 8 * j) * (KSTR * 2);
                ldsm4(bf,     sb + nb + lmoff);
                ldsm4(bf + 4, sb + nb + lmoff + 64);
                c[g][0] = c[g][1] = c[g][2] = c[g][3] = 0.0f;
                #pragma unroll
                for (int k2 = 0; k2 < 4; k2++) {
                    mma16816(c[g], AH[k2], bf + 2 * k2);
                    if (g == 2) mma16816(c[g], AL[k2], bf + 2 * k2);  // lo-pass only for n gate
                }
            }
            // ---- epilogue: units a=8j+2q, b=a+1, rows gid and gid+8 ----
            const float4* pp = pkbase + (4 * j + q) * 6;
            const float4 k0 = pp[0], k1 = pp[1], k2 = pp[2], k3 = pp[3], k4 = pp[4], k5 = pp[5];

            const float ra0 = sigt(fmaf(xp0, k0.x, fmaf(xt0, k0.y, k0.z)) + c[0][0]);
            const float rb0 = sigt(fmaf(xp0, k0.w, fmaf(xt0, k1.x, k1.y)) + c[0][1]);
            const float ra8 = sigt(fmaf(xp8, k0.x, fmaf(xt8, k0.y, k0.z)) + c[0][2]);
            const float rb8 = sigt(fmaf(xp8, k0.w, fmaf(xt8, k1.x, k1.y)) + c[0][3]);

            const float za0 = siga(fmaf(xp0, k1.z, fmaf(xt0, k1.w, k2.x)) + c[1][0]);
            const float zb0 = siga(fmaf(xp0, k2.y, fmaf(xt0, k2.z, k2.w)) + c[1][1]);
            const float za8 = siga(fmaf(xp8, k1.z, fmaf(xt8, k1.w, k2.x)) + c[1][2]);
            const float zb8 = siga(fmaf(xp8, k2.y, fmaf(xt8, k2.z, k2.w)) + c[1][3]);

            const float nva0 = tanha(fmaf(ra0, c[2][0] + k4.z, fmaf(xp0, k3.x, fmaf(xt0, k3.y, k3.z))));
            const float nvb0 = tanha(fmaf(rb0, c[2][1] + k4.w, fmaf(xp0, k3.w, fmaf(xt0, k4.x, k4.y))));
            const float nva8 = tanha(fmaf(ra8, c[2][2] + k4.z, fmaf(xp8, k3.x, fmaf(xt8, k3.y, k3.z))));
            const float nvb8 = tanha(fmaf(rb8, c[2][3] + k4.w, fmaf(xp8, k3.w, fmaf(xt8, k4.x, k4.y))));

            const float nha0 = fmaf(za0, hs0[2*j]   - nva0, nva0);
            const float nhb0 = fmaf(zb0, hs0[2*j+1] - nvb0, nvb0);
            const float nha8 = fmaf(za8, hs8[2*j]   - nva8, nva8);
            const float nhb8 = fmaf(zb8, hs8[2*j+1] - nvb8, nvb8);

            hs0[2*j] = nha0; hs0[2*j+1] = nhb0;
            hs8[2*j] = nha8; hs8[2*j+1] = nhb8;

            y0 = fmaf(k5.x, nha0, fmaf(k5.y, nhb0, y0));
            y8 = fmaf(k5.x, nha8, fmaf(k5.y, nhb8, y8));
        }

        // quad reduce y (lanes within a quad differ only in q)
        y0 += __shfl_xor_sync(0xffffffff, y0, 1);
        y0 += __shfl_xor_sync(0xffffffff, y0, 2);
        y8 += __shfl_xor_sync(0xffffffff, y8, 1);
        y8 += __shfl_xor_sync(0xffffffff, y8, 2);
        if (q == 0) {
            if (v0) out[base + c0] = y0 + ob;
            if (v8) out[base + c8] = y8 + ob;
        }
    }

    // ---- final hidden state (N, 64), fp32 state written directly ----
    float* fo = out + (size_t)T_STEPS * NCELL;
    #pragma unroll
    for (int j = 0; j < 8; j++) {
        const int u = 8 * j + 2 * q;
        if (v0) *(float2*)(fo + (size_t)c0 * 64 + u) = make_float2(hs0[2*j], hs0[2*j+1]);
        if (v8) *(float2*)(fo + (size_t)c8 * 64 + u) = make_float2(hs8[2*j], hs8[2*j+1]);
    }
}

extern "C" void kernel_launch(void* const* d_in, const int* in_sizes, int n_in,
                              void* d_out, int out_size) {
    const float* pr     = (const float*)d_in[0];
    const float* te     = (const float*)d_in[1];
    const float* wih    = (const float*)d_in[2];
    const float* whh    = (const float*)d_in[3];
    const float* bias   = (const float*)d_in[4];
    const float* bias_n = (const float*)d_in[5];
    const float* outw   = (const float*)d_in[6];
    const float* outb   = (const float*)d_in[7];
    const float* init_h = (const float*)d_in[8];
    float* out = (float*)d_out;

    cudaFuncSetAttribute(gru_mma_kernel,
                         cudaFuncAttributeMaxDynamicSharedMemorySize, SMEM_BYTES);

    gru_mma_kernel<<<GRID, BD, SMEM_BYTES>>>(pr, te, wih, whh, bias, bias_n,
                                             outw, outb, init_h, out);
}

// round 12
// speedup vs baseline: 1.5265x; 1.0064x over previous
#include <cuda_runtime.h>
#include <cuda_fp16.h>
#include <cstdint>

#define T_STEPS 365
#define NCELL   65536
#define BD      224      // 7 warps * 32
#define CPB     112      // cells per block (7 warps * 16)
#define GRID    586      // ceil(65536/112)
#define KSTR    88       // padded k stride (fp16 elems): 64 Whh + 16 x-chunk + pad
#define ROWB    (KSTR*2) // 176 bytes per row
#define GSTRIDE (64*ROWB)// 11264 bytes per gate block

#define NW_ROWS 256      // r(64) z(64) n(64) + in-gate x-rows(64)
#define OFF_PK  (NW_ROWS*ROWB)          // 45056
#define SMEM_BYTES (OFF_PK + 32*16)     // 45568

// ---------- helpers ----------
__device__ __forceinline__ uint32_t smem_u32(const void* p) {
    uint32_t r;
    asm("{ .reg .u64 t; cvta.to.shared.u64 t, %1; cvt.u32.u64 %0, t; }" : "=r"(r) : "l"(p));
    return r;
}
__device__ __forceinline__ uint32_t h2u(__half2 h) { return *(uint32_t*)&h; }

__device__ __forceinline__ void mma16816(float* c, const uint32_t* a, const uint32_t* b) {
    asm volatile(
        "mma.sync.aligned.m16n8k16.row.col.f32.f16.f16.f32 "
        "{%0,%1,%2,%3}, {%4,%5,%6,%7}, {%8,%9}, {%0,%1,%2,%3};"
        : "+f"(c[0]), "+f"(c[1]), "+f"(c[2]), "+f"(c[3])
        : "r"(a[0]), "r"(a[1]), "r"(a[2]), "r"(a[3]), "r"(b[0]), "r"(b[1]));
}
__device__ __forceinline__ void ldsm4(uint32_t* r, uint32_t addr) {
    asm volatile("ldmatrix.sync.aligned.m8n8.x4.shared.b16 {%0,%1,%2,%3}, [%4];"
                 : "=r"(r[0]), "=r"(r[1]), "=r"(r[2]), "=r"(r[3]) : "r"(addr));
}
__device__ __forceinline__ void ldsm2(uint32_t* r, uint32_t addr) {
    asm volatile("ldmatrix.sync.aligned.m8n8.x2.shared.b16 {%0,%1}, [%2];"
                 : "=r"(r[0]), "=r"(r[1]) : "r"(addr));
}
// reset gate only: sigmoid via tanh.approx (1 MUFU, error heavily damped downstream)
__device__ __forceinline__ float sigt(float x) {
    float r;
    asm("tanh.approx.f32 %0, %1;" : "=f"(r) : "f"(0.5f * x));
    return fmaf(0.5f, r, 0.5f);
}
// accurate sigmoid: 1/(1+2^(-x*log2e))  (2 MUFU, err ~1e-6)
__device__ __forceinline__ float siga(float x) {
    float e, r;
    asm("ex2.approx.f32 %0, %1;" : "=f"(e) : "f"(-1.4426950408889634f * x));
    asm("rcp.approx.f32 %0, %1;" : "=f"(r) : "f"(e + 1.0f));
    return r;
}
// accurate tanh: 1 - 2/(e^{2x}+1)  (2 MUFU, err ~1e-6)
__device__ __forceinline__ float tanha(float x) {
    float e, r;
    asm("ex2.approx.f32 %0, %1;" : "=f"(e) : "f"(2.8853900817779268f * x));
    asm("rcp.approx.f32 %0, %1;" : "=f"(r) : "f"(e + 1.0f));
    return fmaf(-2.0f, r, 1.0f);
}

extern __shared__ char smc[];

__global__ __launch_bounds__(BD, 2)
void gru_mma_kernel(const float* __restrict__ pr, const float* __restrict__ te,
                    const float* __restrict__ wih, const float* __restrict__ whh,
                    const float* __restrict__ bias, const float* __restrict__ bias_n,
                    const float* __restrict__ outw, const float* __restrict__ outb,
                    const float* __restrict__ init_h, float* __restrict__ out) {
    const int tid = threadIdx.x;

    // ---- zero the whole W tile (covers pads + zero K columns) ----
    for (int i = tid; i < NW_ROWS * (KSTR / 2); i += BD)
        ((uint32_t*)smc)[i] = 0u;
    __syncthreads();

    // ---- W_hh fp16: rows 0..191, k 0..63 ----
    for (int p = tid; p < 192 * 32; p += BD) {
        int n = p >> 5, kp = p & 31;
        __half2 w = __floats2half2_rn(whh[n * 64 + 2 * kp], whh[n * 64 + 2 * kp + 1]);
        *(uint32_t*)(smc + (uint32_t)n * ROWB + 4 * kp) = h2u(w);
    }
    // ---- x-chunk (k64..66 = wih0, wih1, bias) for rows 0..191 (used by r,z) ----
    for (int u = tid; u < 192; u += BD) {
        *(uint32_t*)(smc + (uint32_t)u * ROWB + 128) = h2u(__floats2half2_rn(wih[2*u], wih[2*u+1]));
        *(uint32_t*)(smc + (uint32_t)u * ROWB + 132) = h2u(__floats2half2_rn(bias[u], 0.0f));
    }
    // ---- in-gate x rows 192..255: x-chunk only (n-gate's wih + bias) ----
    for (int u = tid; u < 64; u += BD) {
        int rr = 192 + u, s = 128 + u;
        *(uint32_t*)(smc + (uint32_t)rr * ROWB + 128) = h2u(__floats2half2_rn(wih[2*s], wih[2*s+1]));
        *(uint32_t*)(smc + (uint32_t)rr * ROWB + 132) = h2u(__floats2half2_rn(bias[s], 0.0f));
    }
    // ---- pk[4j+q] = {bias_n[a], bias_n[b], outw[a], outw[b]}, a=8j+2q ----
    if (tid < 32) {
        int j = tid >> 2, q = tid & 3, a = 8 * j + 2 * q;
        ((float4*)(smc + OFF_PK))[tid] = make_float4(bias_n[a], bias_n[a+1], outw[a], outw[a+1]);
    }
    __syncthreads();

    const int warp = tid >> 5, lane = tid & 31;
    const int gid = lane >> 2, q = lane & 3;
    const int cellbase = blockIdx.x * CPB + warp * 16;
    const int c0 = cellbase + gid, c8 = c0 + 8;
    const int c0c = min(c0, NCELL - 1), c8c = min(c8, NCELL - 1);
    const bool v0 = c0 < NCELL, v8 = c8 < NCELL;

    const uint32_t sb = smem_u32(smc);
    const uint32_t lmoff = (uint32_t)((lane & 7) * KSTR + (lane >> 3) * 8) * 2;
    const float4* pkbase = (const float4*)(smc + OFF_PK);

    // ---- fp32 hidden state: hs0/hs8[2j+{0,1}] = h[row gid / gid+8][unit 8j+2q+{0,1}]
    float hs0[16], hs8[16];
    #pragma unroll
    for (int j = 0; j < 8; j++) {
        const int u = 8 * j + 2 * q;
        hs0[2*j] = init_h[u]; hs0[2*j+1] = init_h[u + 1];
        hs8[2*j] = init_h[u]; hs8[2*j+1] = init_h[u + 1];
    }
    const float ob = outb[0];

    for (int t = 0; t < T_STEPS; t++) {
        const size_t base = (size_t)t * NCELL;
        const float xp0 = pr[base + c0c], xp8 = pr[base + c8c];
        const float xt0 = te[base + c0c], xt8 = te[base + c8c];

        // ---- pack frozen fp16 hi/lo A fragments from fp32 state ----
        uint32_t AH[4][4], AL[4][4];
        #pragma unroll
        for (int kt = 0; kt < 4; kt++) {
            #pragma unroll
            for (int hh = 0; hh < 2; hh++) {
                const int j = 2 * kt + hh;
                __half2 p0 = __floats2half2_rn(hs0[2*j], hs0[2*j+1]);
                float2 f0 = __half22float2(p0);
                AH[kt][2*hh] = h2u(p0);
                AL[kt][2*hh] = h2u(__floats2half2_rn(hs0[2*j] - f0.x, hs0[2*j+1] - f0.y));
                __half2 p8 = __floats2half2_rn(hs8[2*j], hs8[2*j+1]);
                float2 f8 = __half22float2(p8);
                AH[kt][2*hh+1] = h2u(p8);
                AL[kt][2*hh+1] = h2u(__floats2half2_rn(hs8[2*j] - f8.x, hs8[2*j+1] - f8.y));
            }
        }
        // ---- x-chunk A fragment: k64..79 = [xp, xt, 1, 0, ...] ----
        uint32_t AX[4];
        {
            uint32_t a0 = 0u, a1 = 0u;
            if (q == 0) {
                a0 = h2u(__floats2half2_rn(xp0, xt0));
                a1 = h2u(__floats2half2_rn(xp8, xt8));
            } else if (q == 1) {
                a0 = 0x00003C00u;  // (1.0h, 0.0h)
                a1 = 0x00003C00u;
            }
            AX[0] = a0; AX[1] = a1; AX[2] = 0u; AX[3] = 0u;
        }

        float y0 = 0.0f, y8 = 0.0f;

        #pragma unroll
        for (int j = 0; j < 8; j++) {
            const uint32_t rowb = (uint32_t)(8 * j) * ROWB;
            uint32_t bf[8], bx[2];
            float cr[4], cz[4], cn[4], ci[4];

            // r gate: full preactivation (h-part + x-part + bias) via K-extension
            ldsm4(bf,     sb + rowb + lmoff);
            ldsm4(bf + 4, sb + rowb + lmoff + 64);
            ldsm2(bx,     sb + rowb + lmoff + 128);
            cr[0]=cr[1]=cr[2]=cr[3]=0.0f;
            #pragma unroll
            for (int k2 = 0; k2 < 4; k2++) mma16816(cr, AH[k2], bf + 2 * k2);
            mma16816(cr, AX, bx);

            // z gate
            ldsm4(bf,     sb + rowb + GSTRIDE + lmoff);
            ldsm4(bf + 4, sb + rowb + GSTRIDE + lmoff + 64);
            ldsm2(bx,     sb + rowb + GSTRIDE + lmoff + 128);
            cz[0]=cz[1]=cz[2]=cz[3]=0.0f;
            #pragma unroll
            for (int k2 = 0; k2 < 4; k2++) mma16816(cz, AH[k2], bf + 2 * k2);
            mma16816(cz, AX, bx);

            // n gate: h-part only, hi+lo passes
            ldsm4(bf,     sb + rowb + 2 * GSTRIDE + lmoff);
            ldsm4(bf + 4, sb + rowb + 2 * GSTRIDE + lmoff + 64);
            cn[0]=cn[1]=cn[2]=cn[3]=0.0f;
            #pragma unroll
            for (int k2 = 0; k2 < 4; k2++) {
                mma16816(cn, AH[k2], bf + 2 * k2);
                mma16816(cn, AL[k2], bf + 2 * k2);
            }

            // in_ = x·Wih_n + bias_n-row bias (x-chunk rows 192+)
            ldsm2(bx, sb + rowb + 3 * GSTRIDE + lmoff + 128);
            ci[0]=ci[1]=ci[2]=ci[3]=0.0f;
            mma16816(ci, AX, bx);

            // ---- epilogue ----
            const float4 kk = pkbase[4 * j + q];

            const float ra0 = sigt(cr[0]);
            const float rb0 = sigt(cr[1]);
            const float ra8 = sigt(cr[2]);
            const float rb8 = sigt(cr[3]);

            const float za0 = siga(cz[0]);
            const float zb0 = siga(cz[1]);
            const float za8 = siga(cz[2]);
            const float zb8 = siga(cz[3]);

            const float nva0 = tanha(fmaf(ra0, cn[0] + kk.x, ci[0]));
            const float nvb0 = tanha(fmaf(rb0, cn[1] + kk.y, ci[1]));
            const float nva8 = tanha(fmaf(ra8, cn[2] + kk.x, ci[2]));
            const float nvb8 = tanha(fmaf(rb8, cn[3] + kk.y, ci[3]));

            const float nha0 = fmaf(za0, hs0[2*j]   - nva0, nva0);
            const float nhb0 = fmaf(zb0, hs0[2*j+1] - nvb0, nvb0);
            const float nha8 = fmaf(za8, hs8[2*j]   - nva8, nva8);
            const float nhb8 = fmaf(zb8, hs8[2*j+1] - nvb8, nvb8);

            hs0[2*j] = nha0; hs0[2*j+1] = nhb0;
            hs8[2*j] = nha8; hs8[2*j+1] = nhb8;

            y0 = fmaf(kk.z, nha0, fmaf(kk.w, nhb0, y0));
            y8 = fmaf(kk.z, nha8, fmaf(kk.w, nhb8, y8));
        }

        // quad reduce y (lanes within a quad differ only in q)
        y0 += __shfl_xor_sync(0xffffffff, y0, 1);
        y0 += __shfl_xor_sync(0xffffffff, y0, 2);
        y8 += __shfl_xor_sync(0xffffffff, y8, 1);
        y8 += __shfl_xor_sync(0xffffffff, y8, 2);
        if (q == 0) {
            if (v0) out[base + c0] = y0 + ob;
            if (v8) out[base + c8] = y8 + ob;
        }
    }

    // ---- final hidden state (N, 64), fp32 state written directly ----
    float* fo = out + (size_t)T_STEPS * NCELL;
    #pragma unroll
    for (int j = 0; j < 8; j++) {
        const int u = 8 * j + 2 * q;
        if (v0) *(float2*)(fo + (size_t)c0 * 64 + u) = make_float2(hs0[2*j], hs0[2*j+1]);
        if (v8) *(float2*)(fo + (size_t)c8 * 64 + u) = make_float2(hs8[2*j], hs8[2*j+1]);
    }
}

extern "C" void kernel_launch(void* const* d_in, const int* in_sizes, int n_in,
                              void* d_out, int out_size) {
    const float* pr     = (const float*)d_in[0];
    const float* te     = (const float*)d_in[1];
    const float* wih    = (const float*)d_in[2];
    const float* whh    = (const float*)d_in[3];
    const float* bias   = (const float*)d_in[4];
    const float* bias_n = (const float*)d_in[5];
    const float* outw   = (const float*)d_in[6];
    const float* outb   = (const float*)d_in[7];
    const float* init_h = (const float*)d_in[8];
    float* out = (float*)d_out;

    cudaFuncSetAttribute(gru_mma_kernel,
                         cudaFuncAttributeMaxDynamicSharedMemorySize, SMEM_BYTES);

    gru_mma_kernel<<<GRID, BD, SMEM_BYTES>>>(pr, te, wih, whh, bias, bias_n,
                                             outw, outb, init_h, out);
}

// round 16
// speedup vs baseline: 1.5926x; 1.0433x over previous
#include <cuda_runtime.h>
#include <cuda_fp16.h>
#include <cstdint>

#define T_STEPS 365
#define NCELL   65536
#define BD      224      // 7 warps * 32
#define CPB     112      // cells per block (7 warps * 16)
#define GRID    586      // ceil(65536/112)
#define KSTR    88       // padded k stride (fp16 elems): 64 Whh + 16 x-chunk + pad
#define ROWB    (KSTR*2) // 176 bytes per row
#define GSTRIDE (64*ROWB)// 11264 bytes per gate block

#define NW_ROWS 256      // r(64) z(64) n(64) + in-gate x-rows(64)
#define OFF_PK  (NW_ROWS*ROWB)          // 45056
#define SMEM_BYTES (OFF_PK + 32*16)     // 45568

// ---------- helpers ----------
__device__ __forceinline__ uint32_t smem_u32(const void* p) {
    uint32_t r;
    asm("{ .reg .u64 t; cvta.to.shared.u64 t, %1; cvt.u32.u64 %0, t; }" : "=r"(r) : "l"(p));
    return r;
}
__device__ __forceinline__ uint32_t h2u(__half2 h) { return *(uint32_t*)&h; }

// NOTE: non-volatile on purpose — pure register op; lets ptxas interleave
// the independent gate chains and overlap with epilogue scalar math.
__device__ __forceinline__ void mma16816(float* c, const uint32_t* a, const uint32_t* b) {
    asm("mma.sync.aligned.m16n8k16.row.col.f32.f16.f16.f32 "
        "{%0,%1,%2,%3}, {%4,%5,%6,%7}, {%8,%9}, {%0,%1,%2,%3};"
        : "+f"(c[0]), "+f"(c[1]), "+f"(c[2]), "+f"(c[3])
        : "r"(a[0]), "r"(a[1]), "r"(a[2]), "r"(a[3]), "r"(b[0]), "r"(b[1]));
}
__device__ __forceinline__ void ldsm4(uint32_t* r, uint32_t addr) {
    asm volatile("ldmatrix.sync.aligned.m8n8.x4.shared.b16 {%0,%1,%2,%3}, [%4];"
                 : "=r"(r[0]), "=r"(r[1]), "=r"(r[2]), "=r"(r[3]) : "r"(addr));
}
__device__ __forceinline__ void ldsm2(uint32_t* r, uint32_t addr) {
    asm volatile("ldmatrix.sync.aligned.m8n8.x2.shared.b16 {%0,%1}, [%2];"
                 : "=r"(r[0]), "=r"(r[1]) : "r"(addr));
}
// reset gate only: sigmoid via tanh.approx (1 MUFU, error heavily damped downstream)
__device__ __forceinline__ float sigt(float x) {
    float r;
    asm("tanh.approx.f32 %0, %1;" : "=f"(r) : "f"(0.5f * x));
    return fmaf(0.5f, r, 0.5f);
}
// accurate sigmoid: 1/(1+2^(-x*log2e))  (2 MUFU, err ~1e-6)
__device__ __forceinline__ float siga(float x) {
    float e, r;
    asm("ex2.approx.f32 %0, %1;" : "=f"(e) : "f"(-1.4426950408889634f * x));
    asm("rcp.approx.f32 %0, %1;" : "=f"(r) : "f"(e + 1.0f));
    return r;
}
// accurate tanh: 1 - 2/(e^{2x}+1)  (2 MUFU, err ~1e-6)
__device__ __forceinline__ float tanha(float x) {
    float e, r;
    asm("ex2.approx.f32 %0, %1;" : "=f"(e) : "f"(2.8853900817779268f * x));
    asm("rcp.approx.f32 %0, %1;" : "=f"(r) : "f"(e + 1.0f));
    return fmaf(-2.0f, r, 1.0f);
}

extern __shared__ char smc[];

__global__ __launch_bounds__(BD, 2)
void gru_mma_kernel(const float* __restrict__ pr, const float* __restrict__ te,
                    const float* __restrict__ wih, const float* __restrict__ whh,
                    const float* __restrict__ bias, const float* __restrict__ bias_n,
                    const float* __restrict__ outw, const float* __restrict__ outb,
                    const float* __restrict__ init_h, float* __restrict__ out) {
    const int tid = threadIdx.x;

    // ---- zero the whole W tile (covers pads + zero K columns) ----
    for (int i = tid; i < NW_ROWS * (KSTR / 2); i += BD)
        ((uint32_t*)smc)[i] = 0u;
    __syncthreads();

    // ---- W_hh fp16: rows 0..191, k 0..63 ----
    for (int p = tid; p < 192 * 32; p += BD) {
        int n = p >> 5, kp = p & 31;
        __half2 w = __floats2half2_rn(whh[n * 64 + 2 * kp], whh[n * 64 + 2 * kp + 1]);
        *(uint32_t*)(smc + (uint32_t)n * ROWB + 4 * kp) = h2u(w);
    }
    // ---- x-chunk: k64,65 = wih(hi); k66 = bias(hi); k67 = bias(lo);
    //      k68,69 = wih duplicated (multiplied by x-lo on the A side) ----
    for (int u = tid; u < 192; u += BD) {
        uint32_t wp = h2u(__floats2half2_rn(wih[2*u], wih[2*u+1]));
        float bv = bias[u];
        float bh_ = __half2float(__float2half_rn(bv));
        *(uint32_t*)(smc + (uint32_t)u * ROWB + 128) = wp;
        *(uint32_t*)(smc + (uint32_t)u * ROWB + 132) = h2u(__floats2half2_rn(bv, bv - bh_));
        *(uint32_t*)(smc + (uint32_t)u * ROWB + 136) = wp;
    }
    // ---- in-gate x rows 192..255: n-gate's wih + bias, same hi/lo layout ----
    for (int u = tid; u < 64; u += BD) {
        int rr = 192 + u, s = 128 + u;
        uint32_t wp = h2u(__floats2half2_rn(wih[2*s], wih[2*s+1]));
        float bv = bias[s];
        float bh_ = __half2float(__float2half_rn(bv));
        *(uint32_t*)(smc + (uint32_t)rr * ROWB + 128) = wp;
        *(uint32_t*)(smc + (uint32_t)rr * ROWB + 132) = h2u(__floats2half2_rn(bv, bv - bh_));
        *(uint32_t*)(smc + (uint32_t)rr * ROWB + 136) = wp;
    }
    // ---- pk[4j+q] = {bias_n[a], bias_n[b], outw[a], outw[b]}, a=8j+2q ----
    if (tid < 32) {
        int j = tid >> 2, q = tid & 3, a = 8 * j + 2 * q;
        ((float4*)(smc + OFF_PK))[tid] = make_float4(bias_n[a], bias_n[a+1], outw[a], outw[a+1]);
    }
    __syncthreads();

    const int warp = tid >> 5, lane = tid & 31;
    const int gid = lane >> 2, q = lane & 3;
    const int cellbase = blockIdx.x * CPB + warp * 16;
    const int c0 = cellbase + gid, c8 = c0 + 8;
    const int c0c = min(c0, NCELL - 1), c8c = min(c8, NCELL - 1);
    const bool v0 = c0 < NCELL, v8 = c8 < NCELL;

    const uint32_t sb = smem_u32(smc);
    const uint32_t lmoff = (uint32_t)((lane & 7) * KSTR + (lane >> 3) * 8) * 2;
    const float4* pkbase = (const float4*)(smc + OFF_PK);

    // ---- fp32 hidden state: hs0/hs8[2j+{0,1}] = h[row gid / gid+8][unit 8j+2q+{0,1}]
    float hs0[16], hs8[16];
    #pragma unroll
    for (int j = 0; j < 8; j++) {
        const int u = 8 * j + 2 * q;
        hs0[2*j] = init_h[u]; hs0[2*j+1] = init_h[u + 1];
        hs8[2*j] = init_h[u]; hs8[2*j+1] = init_h[u + 1];
    }
    const float ob = outb[0];

    for (int t = 0; t < T_STEPS; t++) {
        const size_t base = (size_t)t * NCELL;
        const float xp0 = pr[base + c0c], xp8 = pr[base + c8c];
        const float xt0 = te[base + c0c], xt8 = te[base + c8c];

        // ---- pack frozen fp16 hi/lo A fragments from fp32 state ----
        uint32_t AH[4][4], AL[4][4];
        #pragma unroll
        for (int kt = 0; kt < 4; kt++) {
            #pragma unroll
            for (int hh = 0; hh < 2; hh++) {
                const int j = 2 * kt + hh;
                __half2 p0 = __floats2half2_rn(hs0[2*j], hs0[2*j+1]);
                float2 f0 = __half22float2(p0);
                AH[kt][2*hh] = h2u(p0);
                AL[kt][2*hh] = h2u(__floats2half2_rn(hs0[2*j] - f0.x, hs0[2*j+1] - f0.y));
                __half2 p8 = __floats2half2_rn(hs8[2*j], hs8[2*j+1]);
                float2 f8 = __half22float2(p8);
                AH[kt][2*hh+1] = h2u(p8);
                AL[kt][2*hh+1] = h2u(__floats2half2_rn(hs8[2*j] - f8.x, hs8[2*j+1] - f8.y));
            }
        }
        // ---- x-chunk A fragment over k64..79:
        //  q0: k64,65 = (xp, xt) hi  | q1: k66,67 = (1, 1) -> bias hi+lo
        //  q2: k68,69 = (xp, xt) lo  | q3: zero
        uint32_t AX[4];
        {
            uint32_t a0 = 0u, a1 = 0u;
            __half2 hx0 = __floats2half2_rn(xp0, xt0);
            __half2 hx8 = __floats2half2_rn(xp8, xt8);
            if (q == 0) {
                a0 = h2u(hx0);
                a1 = h2u(hx8);
            } else if (q == 1) {
                a0 = 0x3C003C00u;  // (1.0h, 1.0h)
                a1 = 0x3C003C00u;
            } else if (q == 2) {
                float2 f0 = __half22float2(hx0);
                float2 f8 = __half22float2(hx8);
                a0 = h2u(__floats2half2_rn(xp0 - f0.x, xt0 - f0.y));
                a1 = h2u(__floats2half2_rn(xp8 - f8.x, xt8 - f8.y));
            }
            AX[0] = a0; AX[1] = a1; AX[2] = 0u; AX[3] = 0u;
        }

        float y0 = 0.0f, y8 = 0.0f;

        #pragma unroll
        for (int j = 0; j < 8; j++) {
            const uint32_t rowb = (uint32_t)(8 * j) * ROWB;
            uint32_t bf[8], bx[2];
            float cr[4], cz[4], cnH[4], cnL[4], ci[4];

            // r gate: full preactivation (h-part + x-part + bias) via K-extension
            ldsm4(bf,     sb + rowb + lmoff);
            ldsm4(bf + 4, sb + rowb + lmoff + 64);
            ldsm2(bx,     sb + rowb + lmoff + 128);
            cr[0]=cr[1]=cr[2]=cr[3]=0.0f;
            #pragma unroll
            for (int k2 = 0; k2 < 4; k2++) mma16816(cr, AH[k2], bf + 2 * k2);
            mma16816(cr, AX, bx);

            // z gate
            ldsm4(bf,     sb + rowb + GSTRIDE + lmoff);
            ldsm4(bf + 4, sb + rowb + GSTRIDE + lmoff + 64);
            ldsm2(bx,     sb + rowb + GSTRIDE + lmoff + 128);
            cz[0]=cz[1]=cz[2]=cz[3]=0.0f;
            #pragma unroll
            for (int k2 = 0; k2 < 4; k2++) mma16816(cz, AH[k2], bf + 2 * k2);
            mma16816(cz, AX, bx);

            // n gate: h-part only, two independent 4-deep chains (hi, lo)
            ldsm4(bf,     sb + rowb + 2 * GSTRIDE + lmoff);
            ldsm4(bf + 4, sb + rowb + 2 * GSTRIDE + lmoff + 64);
            cnH[0]=cnH[1]=cnH[2]=cnH[3]=0.0f;
            cnL[0]=cnL[1]=cnL[2]=cnL[3]=0.0f;
            #pragma unroll
            for (int k2 = 0; k2 < 4; k2++) {
                mma16816(cnH, AH[k2], bf + 2 * k2);
                mma16816(cnL, AL[k2], bf + 2 * k2);
            }

            // in_ = x·Wih_n + bias (x-chunk rows 192+)
            ldsm2(bx, sb + rowb + 3 * GSTRIDE + lmoff + 128);
            ci[0]=ci[1]=ci[2]=ci[3]=0.0f;
            mma16816(ci, AX, bx);

            // ---- epilogue ----
            const float4 kk = pkbase[4 * j + q];

            const float ra0 = sigt(cr[0]);
            const float rb0 = sigt(cr[1]);
            const float ra8 = sigt(cr[2]);
            const float rb8 = sigt(cr[3]);

            const float za0 = siga(cz[0]);
            const float zb0 = siga(cz[1]);
            const float za8 = siga(cz[2]);
            const float zb8 = siga(cz[3]);

            const float nva0 = tanha(fmaf(ra0, (cnH[0] + cnL[0]) + kk.x, ci[0]));
            const float nvb0 = tanha(fmaf(rb0, (cnH[1] + cnL[1]) + kk.y, ci[1]));
            const float nva8 = tanha(fmaf(ra8, (cnH[2] + cnL[2]) + kk.x, ci[2]));
            const float nvb8 = tanha(fmaf(rb8, (cnH[3] + cnL[3]) + kk.y, ci[3]));

            const float nha0 = fmaf(za0, hs0[2*j]   - nva0, nva0);
            const float nhb0 = fmaf(zb0, hs0[2*j+1] - nvb0, nvb0);
            const float nha8 = fmaf(za8, hs8[2*j]   - nva8, nva8);
            const float nhb8 = fmaf(zb8, hs8[2*j+1] - nvb8, nvb8);

            hs0[2*j] = nha0; hs0[2*j+1] = nhb0;
            hs8[2*j] = nha8; hs8[2*j+1] = nhb8;

            y0 = fmaf(kk.z, nha0, fmaf(kk.w, nhb0, y0));
            y8 = fmaf(kk.z, nha8, fmaf(kk.w, nhb8, y8));
        }

        // quad reduce y (lanes within a quad differ only in q)
        y0 += __shfl_xor_sync(0xffffffff, y0, 1);
        y0 += __shfl_xor_sync(0xffffffff, y0, 2);
        y8 += __shfl_xor_sync(0xffffffff, y8, 1);
        y8 += __shfl_xor_sync(0xffffffff, y8, 2);
        if (q == 0) {
            if (v0) out[base + c0] = y0 + ob;
            if (v8) out[base + c8] = y8 + ob;
        }
    }

    // ---- final hidden state (N, 64), fp32 state written directly ----
    float* fo = out + (size_t)T_STEPS * NCELL;
    #pragma unroll
    for (int j = 0; j < 8; j++) {
        const int u = 8 * j + 2 * q;
        if (v0) *(float2*)(fo + (size_t)c0 * 64 + u) = make_float2(hs0[2*j], hs0[2*j+1]);
        if (v8) *(float2*)(fo + (size_t)c8 * 64 + u) = make_float2(hs8[2*j], hs8[2*j+1]);
    }
}

extern "C" void kernel_launch(void* const* d_in, const int* in_sizes, int n_in,
                              void* d_out, int out_size) {
    const float* pr     = (const float*)d_in[0];
    const float* te     = (const float*)d_in[1];
    const float* wih    = (const float*)d_in[2];
    const float* whh    = (const float*)d_in[3];
    const float* bias   = (const float*)d_in[4];
    const float* bias_n = (const float*)d_in[5];
    const float* outw   = (const float*)d_in[6];
    const float* outb   = (const float*)d_in[7];
    const float* init_h = (const float*)d_in[8];
    float* out = (float*)d_out;

    cudaFuncSetAttribute(gru_mma_kernel,
                         cudaFuncAttributeMaxDynamicSharedMemorySize, SMEM_BYTES);

    gru_mma_kernel<<<GRID, BD, SMEM_BYTES>>>(pr, te, wih, whh, bias, bias_n,
                                             outw, outb, init_h, out);
}